// round 15
// baseline (speedup 1.0000x reference)
#include <cuda_runtime.h>
#include <cuda_bf16.h>
#include <cuda_fp16.h>
#include <math.h>
#include <stdint.h>

// Problem constants
#define TT 512
#define NBATCH 64      // B*A
#define HID 512
#define DIN 512
#define G3 1536        // 3*HID
#define BBATCH 8
#define AAGENT 8
#define LLAYER 2

// ---------------------------------------------------------------------------
// Scratch (device globals; no allocations allowed)
// ---------------------------------------------------------------------------
__device__ float g_XW1[(size_t)TT * NBATCH * G3];   // 192 MB
__device__ float g_XW2[(size_t)TT * NBATCH * G3];   // 192 MB
__device__ float g_ENCF[(size_t)TT * NBATCH * HID]; // 64 MB
__device__ float g_ENCB[(size_t)TT * NBATCH * HID]; // 64 MB
__device__ float g_ENC [(size_t)TT * NBATCH * HID]; // 64 MB
__device__ float g_hsm [NBATCH * HID];
__device__ float g_msg [NBATCH * HID];
__device__ float g_msgrow[NBATCH * G3];             // msg@Wm2fold + bfold
__device__ float g_Wcomb[LLAYER][(size_t)HID * G3]; // Wm[:512]@Wx_c
__device__ float g_Wm2f [LLAYER][(size_t)HID * G3]; // Wm[512:]@Wx_c
__device__ float g_bfold[LLAYER][G3];               // bm@Wx_c + bx_c
// h in mma A-fragment layout (fp16), double-buffered per group.
__device__ uint4 g_hfrag[2][2][4096];
// distributed barrier flags: 4 groups x 64 CTAs x 128B slots
#define FSTR 32
__device__ unsigned g_flags[4][64 * FSTR];
// chunk-ready counters: [2]=comm0, [3]=comm1 (0,1 reserved)
__device__ unsigned g_chunk[4][256];

// ---------------------------------------------------------------------------
// barrier primitives
// ---------------------------------------------------------------------------
__device__ __forceinline__ unsigned ld_acq(const unsigned* p) {
    unsigned v;
    asm volatile("ld.acquire.gpu.global.u32 %0, [%1];" : "=r"(v) : "l"(p) : "memory");
    return v;
}
__device__ __forceinline__ void st_rel(unsigned* p, unsigned v) {
    asm volatile("st.release.gpu.global.u32 [%0], %1;" :: "l"(p), "r"(v) : "memory");
}
__device__ __forceinline__ void red_add_rel(unsigned* p, unsigned v) {
    asm volatile("red.release.gpu.global.add.u32 [%0], %1;" :: "l"(p), "r"(v) : "memory");
}

// ---------------------------------------------------------------------------
// mma helpers
// ---------------------------------------------------------------------------
__device__ __forceinline__ uint32_t sptr(const void* p) {
    return (uint32_t)__cvta_generic_to_shared(p);
}

__device__ __forceinline__ uint32_t packh(float x, float y) {
    __half2 t;
    t.x = __float2half(x);
    t.y = __float2half(y);
    return *(uint32_t*)&t;
}

#define LDSM_X4T(R0, R1, R2, R3, ADDR)                                         \
    asm volatile("ldmatrix.sync.aligned.m8n8.x4.trans.shared.b16 "             \
                 "{%0,%1,%2,%3},[%4];"                                         \
                 : "=r"(R0), "=r"(R1), "=r"(R2), "=r"(R3) : "r"(ADDR))

#define LDSM_X4(R0, R1, R2, R3, ADDR)                                          \
    asm volatile("ldmatrix.sync.aligned.m8n8.x4.shared.b16 {%0,%1,%2,%3},[%4];"\
                 : "=r"(R0), "=r"(R1), "=r"(R2), "=r"(R3) : "r"(ADDR))

#define LDSM_X2T(R0, R1, ADDR)                                                 \
    asm volatile("ldmatrix.sync.aligned.m8n8.x2.trans.shared.b16 {%0,%1},[%2];"\
                 : "=r"(R0), "=r"(R1) : "r"(ADDR))

#define MMAF16(C0, C1, C2, C3, A0, A1, A2_, A3, B0, B1)                        \
    asm volatile("mma.sync.aligned.m16n8k16.row.col.f32.f16.f16.f32 "          \
                 "{%0,%1,%2,%3},{%4,%5,%6,%7},{%8,%9},{%0,%1,%2,%3};"          \
                 : "+f"(C0), "+f"(C1), "+f"(C2), "+f"(C3)                      \
                 : "r"(A0), "r"(A1), "r"(A2_), "r"(A3), "r"(B0), "r"(B1))

// ---------------------------------------------------------------------------
// Tensor-core GEMM body: A fp16 single-pass, B fp16 hi + residual lo
// (2 mma passes). Double-buffered smem: one __syncthreads per k-tile;
// staging stores overlap mma issue. 128x128 tile, 256 threads.
// ---------------------------------------------------------------------------
#define TG_BUF 12288   // halves per buffer set (A 4096 + Bh 4096 + Bl 4096)

__device__ void tgemm_body(
    char* smbase,
    const float* __restrict__ A, const float* __restrict__ A2,
    const float* __restrict__ Bm, const float* __restrict__ bias,
    const float* __restrict__ rowAdd, float* __restrict__ C,
    int M, int K, int Nc, int revT, int bxIdx, int byIdx)
{
    __half* S = (__half*)smbase;  // [2][12288]: per buffer A,Bh,Bl

    const int tid  = threadIdx.x;
    const int lane = tid & 31;
    const int warp = tid >> 5;
    const int warpM = warp >> 2;
    const int warpN = warp & 3;
    const int row0 = byIdx * 128;
    const int col0 = bxIdx * 128;
    const int lda = (A2 != nullptr) ? 512 : K;

    float acc[4][4][4];
#pragma unroll
    for (int mt = 0; mt < 4; mt++)
#pragma unroll
        for (int nt = 0; nt < 4; nt++)
#pragma unroll
            for (int q = 0; q < 4; q++) acc[mt][nt][q] = 0.f;

    const int g = lane >> 3, r = lane & 7;

    float4 va[4], vb[4];

    auto loadTiles = [&](int k0) {
#pragma unroll
        for (int e = 0; e < 4; e++) {
            int id = e * 256 + tid;
            int m  = id >> 3;
            int k  = (id & 7) << 2;
            float4 v = make_float4(0.f, 0.f, 0.f, 0.f);
            int gm = row0 + m;
            if (gm < M) {
                int kk = k0 + k;
                const float* Ap = A;
                int ka = kk;
                if (A2 != nullptr && kk >= 512) { Ap = A2; ka = kk - 512; }
                int mp = gm;
                if (revT) mp = (511 - (gm >> 6)) * 64 + (gm & 63);
                v = *(const float4*)(Ap + (size_t)mp * lda + ka);
            }
            va[e] = v;
        }
#pragma unroll
        for (int e = 0; e < 4; e++) {
            int id = e * 256 + tid;
            int k  = id >> 5;
            int n  = (id & 31) << 2;
            vb[e] = *(const float4*)(Bm + (size_t)(k0 + k) * Nc + col0 + n);
        }
    };

    auto storeTiles = [&](int buf) {
        __half* Ah = S + buf * TG_BUF;
        __half* Bh = Ah + 4096;
        __half* Bl = Bh + 4096;
#pragma unroll
        for (int e = 0; e < 4; e++) {
            int id = e * 256 + tid;
            int m  = id >> 3;
            int k  = (id & 7) << 2;
            float4 v = va[e];
            uint2 hi;
            hi.x = packh(v.x, v.y);
            hi.y = packh(v.z, v.w);
            int off = (((k >> 3) << 4) + (m >> 3)) * 64 + ((m & 7) << 3) + (k & 7);
            *(uint2*)(Ah + off) = hi;
        }
#pragma unroll
        for (int e = 0; e < 4; e++) {
            int id = e * 256 + tid;
            int k  = id >> 5;
            int n  = (id & 31) << 2;
            float4 v = vb[e];
            float fh0 = __half2float(__float2half(v.x));
            float fh1 = __half2float(__float2half(v.y));
            float fh2 = __half2float(__float2half(v.z));
            float fh3 = __half2float(__float2half(v.w));
            uint2 hi, lo;
            hi.x = packh(v.x, v.y);
            hi.y = packh(v.z, v.w);
            lo.x = packh(v.x - fh0, v.y - fh1);
            lo.y = packh(v.z - fh2, v.w - fh3);
            int off = (((k >> 3) << 4) + (n >> 3)) * 64 + ((k & 7) << 3) + (n & 7);
            *(uint2*)(Bh + off) = hi;
            *(uint2*)(Bl + off) = lo;
        }
    };

    const int nk = K >> 5;
    loadTiles(0);
    storeTiles(0);
    __syncthreads();

    for (int ktile = 0; ktile < nk; ktile++) {
        const int cur = ktile & 1;
        __half* Ah = S + cur * TG_BUF;
        __half* Bh = Ah + 4096;
        __half* Bl = Bh + 4096;
        if (ktile + 1 < nk) loadTiles((ktile + 1) << 5);

#pragma unroll
        for (int kc = 0; kc < 2; kc++) {
            uint32_t bh[8], bl[8];
#pragma unroll
            for (int np = 0; np < 2; np++) {
                int k8 = kc * 2 + (g & 1);
                int n8 = warpN * 4 + np * 2 + (g >> 1);
                int elem = (k8 * 16 + n8) * 64 + r * 8;
                uint32_t ad = sptr(Bh + elem);
                LDSM_X4T(bh[np * 4 + 0], bh[np * 4 + 1],
                         bh[np * 4 + 2], bh[np * 4 + 3], ad);
                ad = sptr(Bl + elem);
                LDSM_X4T(bl[np * 4 + 0], bl[np * 4 + 1],
                         bl[np * 4 + 2], bl[np * 4 + 3], ad);
            }
#pragma unroll
            for (int mt = 0; mt < 4; mt++) {
                int m8 = warpM * 8 + mt * 2 + (g & 1);
                int k8 = kc * 2 + (g >> 1);
                int elem = (k8 * 16 + m8) * 64 + r * 8;
                uint32_t ah[4];
                uint32_t ad = sptr(Ah + elem);
                LDSM_X4(ah[0], ah[1], ah[2], ah[3], ad);
#pragma unroll
                for (int nt = 0; nt < 4; nt++) {
                    float* c = acc[mt][nt];
                    MMAF16(c[0], c[1], c[2], c[3],
                           ah[0], ah[1], ah[2], ah[3], bh[nt * 2], bh[nt * 2 + 1]);
                    MMAF16(c[0], c[1], c[2], c[3],
                           ah[0], ah[1], ah[2], ah[3], bl[nt * 2], bl[nt * 2 + 1]);
                }
            }
        }

        if (ktile + 1 < nk) storeTiles((ktile + 1) & 1);  // other buffer
        __syncthreads();
    }

#pragma unroll
    for (int mt = 0; mt < 4; mt++) {
#pragma unroll
        for (int nt = 0; nt < 4; nt++) {
            int rA = row0 + warpM * 64 + mt * 16 + (lane >> 2);
            int cg = col0 + warpN * 32 + nt * 8 + ((lane & 3) << 1);
            float b0 = 0.f, b1 = 0.f;
            if (bias) { b0 = bias[cg]; b1 = bias[cg + 1]; }
#pragma unroll
            for (int half = 0; half < 2; half++) {
                int m = rA + half * 8;
                if (m >= M) continue;
                float v0 = acc[mt][nt][half * 2 + 0] + b0;
                float v1 = acc[mt][nt][half * 2 + 1] + b1;
                if (rowAdd) {
                    int rm = (m & 63) * Nc;
                    v0 += rowAdd[rm + cg];
                    v1 += rowAdd[rm + cg + 1];
                }
                float2 o; o.x = v0; o.y = v1;
                *(float2*)(C + (size_t)m * Nc + cg) = o;
            }
        }
    }
}

__global__ __launch_bounds__(256) void tgemm(
    const float* A, const float* A2, const float* Bm, const float* bias,
    const float* rowAdd, float* C, int M, int K, int Nc, int revT)
{
    extern __shared__ char smem[];
    tgemm_body(smem, A, A2, Bm, bias, rowAdd, C, M, K, Nc, revT,
               blockIdx.x, blockIdx.y);
}

// ---------------------------------------------------------------------------
// Persistent GRU scanner (fp16 SINGLE-pass recurrent GEMM: h fp16, Wh fp16;
// fp32 recurrence carry); optional per-chunk gating on producer XW.
// ---------------------------------------------------------------------------
struct GruArgs {
    const float* XW;        // [T, 64, 1536]
    const float* Wh;        // [512, 1536]
    const float* bh;        // [1536]
    float* OUT;             // [T, 64, 512]
    uint4* hb0;             // parity-0 fragment buffer (4096 uint4)
    uint4* hb1;             // parity-1
    unsigned* flags;        // [64 * FSTR]
    int rev;
};

struct ProdArgs {
    const float* A;         // enc input [32768, 512]
    const float* B;         // Wcomb [512, 1536]
    const float* rowAdd;    // msgRow [64, 1536]
    float* C;               // XW out
    unsigned* chunk;        // [256]
    int nProd;
};

// smem byte offsets (scanner): WhHi 24576B, part 12800B, bhs 96B
// (gru_fused producers reuse smraw for the 48KB double-buffered tgemm)
#define S_WHHI 0
#define S_PART 24576
#define S_BHS  37376
#define S_TOTAL 49152

__device__ void gru_scan(char* smraw, const GruArgs a, int cpg, int bl,
                         const unsigned* chunk)
{
    __half* WhHi = (__half*)(smraw + S_WHHI);
    float* part = (float*)(smraw + S_PART);   // [2][64*25]
    float* bhs  = (float*)(smraw + S_BHS);    // [24]

    const int tid  = threadIdx.x;
    const int lane = tid & 31;
    const int warp = tid >> 5;
    const int u0 = bl * 8;

    // one-time: Wh slice -> smem fp16 (ldmatrix-tiled, 3 n8 blocks)
    for (int idx = tid; idx < 512 * 24; idx += 256) {
        int d = idx / 24, c = idx - d * 24;
        int u = c / 3, gg = c - u * 3;
        float v = a.Wh[(size_t)d * G3 + gg * 512 + u0 + u];
        int off = ((d >> 3) * 3 + (c >> 3)) * 64 + (d & 7) * 8 + (c & 7);
        WhHi[off] = __float2half(v);
    }
    if (tid < 24) {
        int u = tid / 3, gg = tid - u * 3;
        bhs[tid] = a.bh[gg * 512 + u0 + u];
    }
    // zero my slice of the parity-1 buffer (h_{-1} = 0)
    {
        int zn = 4096 / cpg;
        uint4 z; z.x = z.y = z.z = z.w = 0u;
        for (int i = tid; i < zn; i += 256) a.hb1[bl * zn + i] = z;
    }
    __syncthreads();
    if (tid == 0) st_rel(&a.flags[bl * FSTR], 1u);

    // per-thread constants
    const int kh = warp >> 2;      // K half (0/1)
    const int mt = warp & 3;       // mtile (rows mt*16..+15)
    const int g  = lane >> 3, r = lane & 7;
    const int g01 = g & 1;
    const int rowI = tid >> 3;     // gate item 0 row (0..31)
    const int uI   = tid & 7;
    const int cb   = uI * 3;
    const float bhr = bhs[cb], bhz = bhs[cb + 1], bhn = bhs[cb + 2];

    // poll addresses for warp 0 (2 slots per lane)
    const unsigned* fp0 = a.flags + (2 * lane) * FSTR;
    const unsigned* fp1 = a.flags + (2 * lane + 1) * FSTR;

    // producer scatter offsets (byte) for q=0,1
    int oQ[2];
    {
        int u = u0 + uI;
        int khp = u >> 8, ktp = (u >> 4) & 15, k_in = u & 15;
#pragma unroll
        for (int q = 0; q < 2; q++) {
            int row = rowI + q * 32;
            int mtp = row >> 4, m_in = row & 15;
            int lanep = (m_in & 7) * 4 + ((k_in & 7) >> 1);
            int regp = ((m_in >> 3) & 1) + (((k_in >> 3) & 1) << 1);
            oQ[q] = ((((khp * 16 + ktp) * 4 + mtp) * 32 + lanep) << 4)
                    + regp * 4 + (k_in & 1) * 2;
        }
    }
    float hp0 = 0.f, hp1 = 0.f;

    for (int s = 0; s < TT; s++) {
        float xw0r, xw0z, xw0n, xw1r, xw1z, xw1n;
        auto loadXW = [&]() {
            const float* p0 = a.XW + ((size_t)s * 64 + rowI) * G3 + u0 + uI;
            const float* p1 = p0 + (size_t)32 * G3;
            xw0r = p0[0]; xw0z = p0[512]; xw0n = p0[1024];
            xw1r = p1[0]; xw1z = p1[512]; xw1n = p1[1024];
        };
        // Prefetch XW before the poll whenever its readiness is already
        // known: always in static-XW mode; at odd steps in fused mode.
        const bool early = (!chunk) || (s & 1);
        if (early) loadXW();

        // wait: all h_{s-1} published (and XW chunk ready in fused mode)
        if (warp == 0) {
            const unsigned tgt = (unsigned)(s + 1);
            if (chunk && !(s & 1)) {
                const unsigned* cc = &chunk[s >> 1];
                for (;;) {
                    unsigned v0 = ld_acq(fp0);
                    unsigned v1 = ld_acq(fp1);
                    unsigned c0 = ld_acq(cc);
                    if (__all_sync(0xffffffffu,
                                   v0 >= tgt && v1 >= tgt && c0 >= 12u)) break;
                }
            } else {
                for (;;) {
                    unsigned v0 = ld_acq(fp0);
                    unsigned v1 = ld_acq(fp1);
                    if (__all_sync(0xffffffffu, v0 >= tgt && v1 >= tgt)) break;
                }
            }
        }
        __syncthreads();

        // prefetch ALL A-fragments (16 x LDG.128, MLP-batched)
        const uint4* rb = (s & 1) ? a.hb0 : a.hb1;
        uint4 AH[16];
        {
            const uint4* base = rb + (kh * 16 * 4 + mt) * 32 + lane;
#pragma unroll
            for (int kt = 0; kt < 16; kt++) AH[kt] = base[kt * 128];
        }
        if (!early) loadXW();   // fused even step: after chunk gate

        float acc[3][4];
#pragma unroll
        for (int nt = 0; nt < 3; nt++)
#pragma unroll
            for (int q = 0; q < 4; q++) acc[nt][q] = 0.f;

#pragma unroll
        for (int kt = 0; kt < 16; kt++) {
            const int k8a = kh * 32 + kt * 2;
            uint32_t bh6[6];
            {
                int k8 = k8a + (g & 1);
                int n8 = g >> 1;
                int elem = (k8 * 3 + n8) * 64 + r * 8;
                uint32_t bd = sptr(WhHi + elem);
                LDSM_X4T(bh6[0], bh6[1], bh6[2], bh6[3], bd);
                int k8c = k8a + g01;
                int elem2 = (k8c * 3 + 2) * 64 + r * 8;
                bd = sptr(WhHi + elem2);
                LDSM_X2T(bh6[4], bh6[5], bd);
            }
#pragma unroll
            for (int nt = 0; nt < 3; nt++) {
                float* c = acc[nt];
                MMAF16(c[0], c[1], c[2], c[3],
                       AH[kt].x, AH[kt].y, AH[kt].z, AH[kt].w,
                       bh6[nt * 2], bh6[nt * 2 + 1]);
            }
        }

        // write partials to smem
        {
            float* pb = part + kh * 1600;
            int prow = mt * 16 + (lane >> 2);
            int pc = (lane & 3) * 2;
#pragma unroll
            for (int nt = 0; nt < 3; nt++) {
                pb[prow * 25 + nt * 8 + pc]     = acc[nt][0];
                pb[prow * 25 + nt * 8 + pc + 1] = acc[nt][1];
                pb[(prow + 8) * 25 + nt * 8 + pc]     = acc[nt][2];
                pb[(prow + 8) * 25 + nt * 8 + pc + 1] = acc[nt][3];
            }
        }
        __syncthreads();

        // gates: 2 items per thread (rows rowI, rowI+32; unit uI)
        char* wb = (char*)((s & 1) ? a.hb1 : a.hb0);
        float hn0, hn1;
#pragma unroll
        for (int q = 0; q < 2; q++) {
            int row = rowI + q * 32;
            float gr = part[row * 25 + cb]     + part[1600 + row * 25 + cb];
            float gz = part[row * 25 + cb + 1] + part[1600 + row * 25 + cb + 1];
            float gn = part[row * 25 + cb + 2] + part[1600 + row * 25 + cb + 2];
            float xr = q ? xw1r : xw0r;
            float xz = q ? xw1z : xw0z;
            float xn = q ? xw1n : xw0n;
            float rr = __fdividef(1.f, 1.f + __expf(-(xr + gr + bhr)));
            float zz = __fdividef(1.f, 1.f + __expf(-(xz + gz + bhz)));
            float tt = xn + rr * (gn + bhn);
            float nn = __fdividef(2.f, 1.f + __expf(-2.f * tt)) - 1.f;
            float hp = q ? hp1 : hp0;
            float hn = (1.f - zz) * nn + zz * hp;
            if (q) { hp1 = hn; hn1 = hn; } else { hp0 = hn; hn0 = hn; }
            *(__half*)(wb + oQ[q]) = __float2half(hn);
        }
        __syncthreads();
        if (s < TT - 1 && tid == 0) st_rel(&a.flags[bl * FSTR], (unsigned)(s + 2));

        // OUT (f32) stores off the critical path
        const int oidx = a.rev ? (TT - 1 - s) : s;
        a.OUT[((size_t)oidx * NBATCH + rowI) * HID + u0 + uI] = hn0;
        a.OUT[((size_t)oidx * NBATCH + rowI + 32) * HID + u0 + uI] = hn1;
    }
}

__global__ __launch_bounds__(256, 1) void gru_tc(GruArgs a0, GruArgs a1, int cpg)
{
    extern __shared__ char smraw[];
    const bool second = (blockIdx.x / cpg) != 0;
    gru_scan(smraw, second ? a1 : a0, cpg, blockIdx.x % cpg, nullptr);
}

// Fused comm-layer kernel: CTAs 0..63 scan; CTAs 64..147 produce XW tiles in
// timestep order, publishing per-chunk (2 timesteps) ready counters.
__global__ __launch_bounds__(256, 1) void gru_fused(GruArgs a, ProdArgs pr)
{
    extern __shared__ char smraw[];
    if (blockIdx.x < 64) {
        gru_scan(smraw, a, 64, blockIdx.x, pr.chunk);
        return;
    }
    const int p = blockIdx.x - 64;
    for (int t = p; t < 3072; t += pr.nProd) {
        int c = t / 12, n = t - c * 12;
        tgemm_body(smraw, pr.A, nullptr, pr.B, nullptr, pr.rowAdd, pr.C,
                   TT * NBATCH, HID, G3, 0, n, c);
        __syncthreads();
        if (threadIdx.x == 0) red_add_rel(&pr.chunk[c], 1u);
    }
}

// reset barrier flags + chunk counters for graph-replay determinism
__global__ void reset_flags_kernel()
{
    int i = blockIdx.x * blockDim.x + threadIdx.x;
    if (i < 4 * 64 * FSTR) ((unsigned*)g_flags)[i] = 0u;
    if (i < 4 * 256) ((unsigned*)g_chunk)[i] = 0u;
}

// ---------------------------------------------------------------------------
// msg / lasth
// ---------------------------------------------------------------------------
__global__ void msg_kernel(const float* __restrict__ h, float* __restrict__ msg)
{
    int idx = blockIdx.x * blockDim.x + threadIdx.x;
    if (idx >= NBATCH * HID) return;
    int n = idx >> 9, j = idx & 511;
    int b = n >> 3;
    float s = 0.f;
#pragma unroll
    for (int aa = 0; aa < AAGENT; aa++) s += h[((b << 3) + aa) * HID + j];
    msg[idx] = (s - h[n * HID + j]) * (1.f / (AAGENT - 1));
}

__global__ void lasth_kernel(const float* __restrict__ OUT, float* __restrict__ dst)
{
    int idx = blockIdx.x * blockDim.x + threadIdx.x;
    if (idx >= BBATCH * HID) return;
    int b = idx >> 9, j = idx & 511;
    dst[idx] = OUT[((size_t)(TT - 1) * NBATCH + b * AAGENT) * HID + j];
}

// ---------------------------------------------------------------------------
// launch
// ---------------------------------------------------------------------------
extern "C" void kernel_launch(void* const* d_in, const int* in_sizes, int n_in,
                              void* d_out, int out_size)
{
    const float* article = (const float*)d_in[0];
    const float* Wx_f = (const float*)d_in[2];
    const float* Wh_f = (const float*)d_in[3];
    const float* bx_f = (const float*)d_in[4];
    const float* bh_f = (const float*)d_in[5];
    const float* Wx_b = (const float*)d_in[6];
    const float* Wh_b = (const float*)d_in[7];
    const float* bx_b = (const float*)d_in[8];
    const float* bh_b = (const float*)d_in[9];
    const float* Wp   = (const float*)d_in[10];
    const float* bp   = (const float*)d_in[11];
    const float* Wm   = (const float*)d_in[12];
    const float* bm   = (const float*)d_in[13];
    const float* Wx_c = (const float*)d_in[14];
    const float* Wh_c = (const float*)d_in[15];
    const float* bx_c = (const float*)d_in[16];
    const float* bh_c = (const float*)d_in[17];

    float *XW1, *XW2, *ENCF, *ENCB, *ENC, *hsm, *msg, *msgrow;
    float *Wcomb, *Wm2f, *bfold;
    uint4* hfrag;
    unsigned *flags, *chunks;
    cudaGetSymbolAddress((void**)&XW1,  g_XW1);
    cudaGetSymbolAddress((void**)&XW2,  g_XW2);
    cudaGetSymbolAddress((void**)&ENCF, g_ENCF);
    cudaGetSymbolAddress((void**)&ENCB, g_ENCB);
    cudaGetSymbolAddress((void**)&ENC,  g_ENC);
    cudaGetSymbolAddress((void**)&hsm,  g_hsm);
    cudaGetSymbolAddress((void**)&msg,  g_msg);
    cudaGetSymbolAddress((void**)&msgrow, g_msgrow);
    cudaGetSymbolAddress((void**)&Wcomb, g_Wcomb);
    cudaGetSymbolAddress((void**)&Wm2f,  g_Wm2f);
    cudaGetSymbolAddress((void**)&bfold, g_bfold);
    cudaGetSymbolAddress((void**)&hfrag, g_hfrag);
    cudaGetSymbolAddress((void**)&flags, g_flags);
    cudaGetSymbolAddress((void**)&chunks, g_chunk);
    uint4* hA0 = hfrag;
    uint4* hA1 = hfrag + 4096;
    uint4* hB0 = hfrag + 8192;
    uint4* hB1 = hfrag + 12288;

    const int M = TT * NBATCH;
    const int SMG = 49152;
    cudaFuncSetAttribute((const void*)tgemm,
                         cudaFuncAttributeMaxDynamicSharedMemorySize, SMG);
    cudaFuncSetAttribute((const void*)gru_tc,
                         cudaFuncAttributeMaxDynamicSharedMemorySize, S_TOTAL);
    cudaFuncSetAttribute((const void*)gru_fused,
                         cudaFuncAttributeMaxDynamicSharedMemorySize, S_TOTAL);

    // 0) weight folding (tiny):
    //    Wcomb[l] = Wm[:512] @ Wx_c[l]
    //    Wm2f[l]  = Wm[512:] @ Wx_c[l]
    //    bfold[l] = bm @ Wx_c[l] + bx_c[l]
    for (int l = 0; l < LLAYER; l++) {
        tgemm<<<dim3(12, 4), 256, SMG>>>(Wm, nullptr, Wx_c + (size_t)l * HID * G3,
                                         nullptr, nullptr,
                                         Wcomb + (size_t)l * HID * G3,
                                         HID, HID, G3, 0);
        tgemm<<<dim3(12, 4), 256, SMG>>>(Wm + (size_t)512 * HID, nullptr,
                                         Wx_c + (size_t)l * HID * G3,
                                         nullptr, nullptr,
                                         Wm2f + (size_t)l * HID * G3,
                                         HID, HID, G3, 0);
        tgemm<<<dim3(12, 1), 256, SMG>>>(bm, nullptr,
                                         Wx_c + (size_t)l * HID * G3,
                                         bx_c + (size_t)l * G3, nullptr,
                                         bfold + (size_t)l * G3,
                                         1, HID, G3, 0);
    }

    // 1) xW precompute for both directions (backward reads time-reversed rows)
    tgemm<<<dim3(G3 / 128, M / 128), 256, SMG>>>(article, nullptr, Wx_f, bx_f,
                                                 nullptr, XW1, M, DIN, G3, 0);
    tgemm<<<dim3(G3 / 128, M / 128), 256, SMG>>>(article, nullptr, Wx_b, bx_b,
                                                 nullptr, XW2, M, DIN, G3, 1);

    // 2) bidirectional recurrence (two 64-CTA barrier groups, one launch)
    GruArgs af{XW1, Wh_f, bh_f, ENCF, hA0, hA1, flags + 0 * 64 * FSTR, 0};
    GruArgs ab{XW2, Wh_b, bh_b, ENCB, hB0, hB1, flags + 1 * 64 * FSTR, 1};
    gru_tc<<<128, 256, S_TOTAL>>>(af, ab, 64);

    // 3) projection of per-step encodings and of final hidden
    tgemm<<<dim3(HID / 128, M / 128), 256, SMG>>>(ENCF, ENCB, Wp, bp, nullptr,
                                                  ENC, M, 2 * HID, HID, 0);
    tgemm<<<dim3(HID / 128, 1), 256, SMG>>>(ENCF + (size_t)(TT - 1) * NBATCH * HID,
                                            ENCB, Wp, bp, nullptr, hsm,
                                            NBATCH, 2 * HID, HID, 0);

    // 4) communication layers (fused producer/scanner); msgRow computed in a
    //    single folded GEMM: msgRow = msg @ Wm2f[l] + bfold[l]
    for (int l = 0; l < LLAYER; l++) {
        const float* hsrc = (l == 0) ? hsm : (ENC + (size_t)(TT - 1) * NBATCH * HID);
        msg_kernel<<<(NBATCH * HID) / 256, 256>>>(hsrc, msg);
        tgemm<<<dim3(G3 / 128, 1), 256, SMG>>>(msg, nullptr,
                                               Wm2f + (size_t)l * HID * G3,
                                               bfold + (size_t)l * G3, nullptr,
                                               msgrow, NBATCH, HID, G3, 0);
        float* outp = (l == LLAYER - 1) ? (float*)d_out : ENC;
        GruArgs ac{XW1, Wh_c + (size_t)l * HID * G3, bh_c + (size_t)l * G3,
                   outp, hA0, hA1, flags + (2 + l) * 64 * FSTR, 0};
        ProdArgs pc{ENC, Wcomb + (size_t)l * HID * G3, msgrow, XW1,
                    chunks + (2 + l) * 256, 84};
        gru_fused<<<148, 256, S_TOTAL>>>(ac, pc);
    }

    // 5) tail output + flag reset for graph replay
    lasth_kernel<<<(BBATCH * HID + 255) / 256, 256>>>(
        (const float*)d_out, (float*)d_out + (size_t)TT * NBATCH * HID);
    reset_flags_kernel<<<32, 256>>>();
}

// round 16
// speedup vs baseline: 1.0155x; 1.0155x over previous
#include <cuda_runtime.h>
#include <cuda_bf16.h>
#include <cuda_fp16.h>
#include <math.h>
#include <stdint.h>

// Problem constants
#define TT 512
#define NBATCH 64      // B*A
#define HID 512
#define DIN 512
#define G3 1536        // 3*HID
#define BBATCH 8
#define AAGENT 8
#define LLAYER 2

// ---------------------------------------------------------------------------
// Scratch (device globals; no allocations allowed)
// ---------------------------------------------------------------------------
__device__ float g_XW1[(size_t)TT * NBATCH * G3];   // 192 MB
__device__ float g_XW2[(size_t)TT * NBATCH * G3];   // 192 MB
__device__ float g_ENCF[(size_t)TT * NBATCH * HID]; // 64 MB
__device__ float g_ENCB[(size_t)TT * NBATCH * HID]; // 64 MB
__device__ float g_ENC [(size_t)TT * NBATCH * HID]; // 64 MB
__device__ float g_hsm [NBATCH * HID];
__device__ float g_msg [NBATCH * HID];
__device__ float g_msgrow[NBATCH * G3];             // msg@Wm2fold + bfold
__device__ float g_Wcomb[LLAYER][(size_t)HID * G3]; // Wm[:512]@Wx_c
__device__ float g_Wm2f [LLAYER][(size_t)HID * G3]; // Wm[512:]@Wx_c
__device__ float g_bfold[LLAYER][G3];               // bm@Wx_c + bx_c
// h in mma A-fragment layout (fp16), double-buffered per group.
__device__ uint4 g_hfrag[2][2][4096];
// distributed barrier flags: 4 groups x 64 CTAs x 128B slots
#define FSTR 32
__device__ unsigned g_flags[4][64 * FSTR];
// chunk-ready counters: [2]=comm0, [3]=comm1 (0,1 reserved)
__device__ unsigned g_chunk[4][256];

// ---------------------------------------------------------------------------
// barrier primitives
// ---------------------------------------------------------------------------
__device__ __forceinline__ unsigned ld_acq(const unsigned* p) {
    unsigned v;
    asm volatile("ld.acquire.gpu.global.u32 %0, [%1];" : "=r"(v) : "l"(p) : "memory");
    return v;
}
__device__ __forceinline__ void st_rel(unsigned* p, unsigned v) {
    asm volatile("st.release.gpu.global.u32 [%0], %1;" :: "l"(p), "r"(v) : "memory");
}
__device__ __forceinline__ void red_add_rel(unsigned* p, unsigned v) {
    asm volatile("red.release.gpu.global.add.u32 [%0], %1;" :: "l"(p), "r"(v) : "memory");
}

// ---------------------------------------------------------------------------
// mma helpers
// ---------------------------------------------------------------------------
__device__ __forceinline__ uint32_t sptr(const void* p) {
    return (uint32_t)__cvta_generic_to_shared(p);
}

__device__ __forceinline__ uint32_t packh(float x, float y) {
    __half2 t;
    t.x = __float2half(x);
    t.y = __float2half(y);
    return *(uint32_t*)&t;
}

#define LDSM_X4T(R0, R1, R2, R3, ADDR)                                         \
    asm volatile("ldmatrix.sync.aligned.m8n8.x4.trans.shared.b16 "             \
                 "{%0,%1,%2,%3},[%4];"                                         \
                 : "=r"(R0), "=r"(R1), "=r"(R2), "=r"(R3) : "r"(ADDR))

#define LDSM_X4(R0, R1, R2, R3, ADDR)                                          \
    asm volatile("ldmatrix.sync.aligned.m8n8.x4.shared.b16 {%0,%1,%2,%3},[%4];"\
                 : "=r"(R0), "=r"(R1), "=r"(R2), "=r"(R3) : "r"(ADDR))

#define LDSM_X2T(R0, R1, ADDR)                                                 \
    asm volatile("ldmatrix.sync.aligned.m8n8.x2.trans.shared.b16 {%0,%1},[%2];"\
                 : "=r"(R0), "=r"(R1) : "r"(ADDR))

#define MMAF16(C0, C1, C2, C3, A0, A1, A2_, A3, B0, B1)                        \
    asm volatile("mma.sync.aligned.m16n8k16.row.col.f32.f16.f16.f32 "          \
                 "{%0,%1,%2,%3},{%4,%5,%6,%7},{%8,%9},{%0,%1,%2,%3};"          \
                 : "+f"(C0), "+f"(C1), "+f"(C2), "+f"(C3)                      \
                 : "r"(A0), "r"(A1), "r"(A2_), "r"(A3), "r"(B0), "r"(B1))

// ---------------------------------------------------------------------------
// Tensor-core GEMM body: A fp16 single-pass, B fp16 hi + residual lo
// (2 mma passes). 128x128 tile. Templated on thread count (256 or 512);
// NT=512 gives 16 warps/SM for the latency-bound standalone launches.
// ---------------------------------------------------------------------------
template <int NT>
__device__ void tgemm_body(
    char* smbase,
    const float* __restrict__ A, const float* __restrict__ A2,
    const float* __restrict__ Bm, const float* __restrict__ bias,
    const float* __restrict__ rowAdd, float* __restrict__ C,
    int M, int K, int Nc, int revT, int bxIdx, int byIdx)
{
    constexpr int MT = 1024 / NT;          // 4 (NT=256) or 2 (NT=512)
    constexpr int EA = 1024 / NT;          // staging iterations

    __half* Ah = (__half*)smbase;          // 4096 half = 8 KB
    __half* Bh = Ah + 4096;
    __half* Bl = Bh + 4096;

    const int tid  = threadIdx.x;
    const int lane = tid & 31;
    const int warp = tid >> 5;
    const int warpM = warp >> 2;
    const int warpN = warp & 3;
    const int row0 = byIdx * 128;
    const int col0 = bxIdx * 128;
    const int lda = (A2 != nullptr) ? 512 : K;

    float acc[MT][4][4];
#pragma unroll
    for (int mt = 0; mt < MT; mt++)
#pragma unroll
        for (int nt = 0; nt < 4; nt++)
#pragma unroll
            for (int q = 0; q < 4; q++) acc[mt][nt][q] = 0.f;

    const int g = lane >> 3, r = lane & 7;

    float4 va[EA], vb[EA];

    auto loadTiles = [&](int k0) {
#pragma unroll
        for (int e = 0; e < EA; e++) {
            int id = e * NT + tid;
            int m  = id >> 3;
            int k  = (id & 7) << 2;
            float4 v = make_float4(0.f, 0.f, 0.f, 0.f);
            int gm = row0 + m;
            if (gm < M) {
                int kk = k0 + k;
                const float* Ap = A;
                int ka = kk;
                if (A2 != nullptr && kk >= 512) { Ap = A2; ka = kk - 512; }
                int mp = gm;
                if (revT) mp = (511 - (gm >> 6)) * 64 + (gm & 63);
                v = *(const float4*)(Ap + (size_t)mp * lda + ka);
            }
            va[e] = v;
        }
#pragma unroll
        for (int e = 0; e < EA; e++) {
            int id = e * NT + tid;
            int k  = id >> 5;
            int n  = (id & 31) << 2;
            vb[e] = *(const float4*)(Bm + (size_t)(k0 + k) * Nc + col0 + n);
        }
    };

    auto storeTiles = [&]() {
#pragma unroll
        for (int e = 0; e < EA; e++) {
            int id = e * NT + tid;
            int m  = id >> 3;
            int k  = (id & 7) << 2;
            float4 v = va[e];
            uint2 hi;
            hi.x = packh(v.x, v.y);
            hi.y = packh(v.z, v.w);
            int off = (((k >> 3) << 4) + (m >> 3)) * 64 + ((m & 7) << 3) + (k & 7);
            *(uint2*)(Ah + off) = hi;
        }
#pragma unroll
        for (int e = 0; e < EA; e++) {
            int id = e * NT + tid;
            int k  = id >> 5;
            int n  = (id & 31) << 2;
            float4 v = vb[e];
            float fh0 = __half2float(__float2half(v.x));
            float fh1 = __half2float(__float2half(v.y));
            float fh2 = __half2float(__float2half(v.z));
            float fh3 = __half2float(__float2half(v.w));
            uint2 hi, lo;
            hi.x = packh(v.x, v.y);
            hi.y = packh(v.z, v.w);
            lo.x = packh(v.x - fh0, v.y - fh1);
            lo.y = packh(v.z - fh2, v.w - fh3);
            int off = (((k >> 3) << 4) + (n >> 3)) * 64 + ((k & 7) << 3) + (n & 7);
            *(uint2*)(Bh + off) = hi;
            *(uint2*)(Bl + off) = lo;
        }
    };

    loadTiles(0);

    for (int k0 = 0; k0 < K; k0 += 32) {
        storeTiles();
        __syncthreads();
        if (k0 + 32 < K) loadTiles(k0 + 32);   // overlap with mma below

#pragma unroll
        for (int kc = 0; kc < 2; kc++) {
            uint32_t bh[8], bl[8];
#pragma unroll
            for (int np = 0; np < 2; np++) {
                int k8 = kc * 2 + (g & 1);
                int n8 = warpN * 4 + np * 2 + (g >> 1);
                int elem = (k8 * 16 + n8) * 64 + r * 8;
                uint32_t ad = sptr(Bh + elem);
                LDSM_X4T(bh[np * 4 + 0], bh[np * 4 + 1],
                         bh[np * 4 + 2], bh[np * 4 + 3], ad);
                ad = sptr(Bl + elem);
                LDSM_X4T(bl[np * 4 + 0], bl[np * 4 + 1],
                         bl[np * 4 + 2], bl[np * 4 + 3], ad);
            }
#pragma unroll
            for (int mt = 0; mt < MT; mt++) {
                int m8 = warpM * 2 * MT + mt * 2 + (g & 1);
                int k8 = kc * 2 + (g >> 1);
                int elem = (k8 * 16 + m8) * 64 + r * 8;
                uint32_t ah[4];
                uint32_t ad = sptr(Ah + elem);
                LDSM_X4(ah[0], ah[1], ah[2], ah[3], ad);
#pragma unroll
                for (int nt = 0; nt < 4; nt++) {
                    float* c = acc[mt][nt];
                    MMAF16(c[0], c[1], c[2], c[3],
                           ah[0], ah[1], ah[2], ah[3], bh[nt * 2], bh[nt * 2 + 1]);
                    MMAF16(c[0], c[1], c[2], c[3],
                           ah[0], ah[1], ah[2], ah[3], bl[nt * 2], bl[nt * 2 + 1]);
                }
            }
        }
        __syncthreads();
    }

#pragma unroll
    for (int mt = 0; mt < MT; mt++) {
#pragma unroll
        for (int nt = 0; nt < 4; nt++) {
            int rA = row0 + warpM * (16 * MT) + mt * 16 + (lane >> 2);
            int cg = col0 + warpN * 32 + nt * 8 + ((lane & 3) << 1);
            float b0 = 0.f, b1 = 0.f;
            if (bias) { b0 = bias[cg]; b1 = bias[cg + 1]; }
#pragma unroll
            for (int half = 0; half < 2; half++) {
                int m = rA + half * 8;
                if (m >= M) continue;
                float v0 = acc[mt][nt][half * 2 + 0] + b0;
                float v1 = acc[mt][nt][half * 2 + 1] + b1;
                if (rowAdd) {
                    int rm = (m & 63) * Nc;
                    v0 += rowAdd[rm + cg];
                    v1 += rowAdd[rm + cg + 1];
                }
                float2 o; o.x = v0; o.y = v1;
                *(float2*)(C + (size_t)m * Nc + cg) = o;
            }
        }
    }
}

__global__ __launch_bounds__(256) void tgemm(
    const float* A, const float* A2, const float* Bm, const float* bias,
    const float* rowAdd, float* C, int M, int K, int Nc, int revT)
{
    extern __shared__ char smem[];
    tgemm_body<256>(smem, A, A2, Bm, bias, rowAdd, C, M, K, Nc, revT,
                    blockIdx.x, blockIdx.y);
}

__global__ __launch_bounds__(512) void tgemm512(
    const float* A, const float* A2, const float* Bm, const float* bias,
    const float* rowAdd, float* C, int M, int K, int Nc, int revT)
{
    extern __shared__ char smem[];
    tgemm_body<512>(smem, A, A2, Bm, bias, rowAdd, C, M, K, Nc, revT,
                    blockIdx.x, blockIdx.y);
}

// ---------------------------------------------------------------------------
// Persistent GRU scanner (fp16 SINGLE-pass recurrent GEMM: h fp16, Wh fp16;
// fp32 recurrence carry); optional per-chunk gating on producer XW.
// ---------------------------------------------------------------------------
struct GruArgs {
    const float* XW;        // [T, 64, 1536]
    const float* Wh;        // [512, 1536]
    const float* bh;        // [1536]
    float* OUT;             // [T, 64, 512]
    uint4* hb0;             // parity-0 fragment buffer (4096 uint4)
    uint4* hb1;             // parity-1
    unsigned* flags;        // [64 * FSTR]
    int rev;
};

struct ProdArgs {
    const float* A;         // enc input [32768, 512]
    const float* B;         // Wcomb [512, 1536]
    const float* rowAdd;    // msgRow [64, 1536]
    float* C;               // XW out
    unsigned* chunk;        // [256]
    int nProd;
};

// smem byte offsets (scanner): WhHi 24576B, part 12800B, bhs 96B
#define S_WHHI 0
#define S_PART 24576
#define S_BHS  37376
#define S_TOTAL 37504

__device__ void gru_scan(char* smraw, const GruArgs a, int cpg, int bl,
                         const unsigned* chunk)
{
    __half* WhHi = (__half*)(smraw + S_WHHI);
    float* part = (float*)(smraw + S_PART);   // [2][64*25]
    float* bhs  = (float*)(smraw + S_BHS);    // [24]

    const int tid  = threadIdx.x;
    const int lane = tid & 31;
    const int warp = tid >> 5;
    const int u0 = bl * 8;

    // one-time: Wh slice -> smem fp16 (ldmatrix-tiled, 3 n8 blocks)
    for (int idx = tid; idx < 512 * 24; idx += 256) {
        int d = idx / 24, c = idx - d * 24;
        int u = c / 3, gg = c - u * 3;
        float v = a.Wh[(size_t)d * G3 + gg * 512 + u0 + u];
        int off = ((d >> 3) * 3 + (c >> 3)) * 64 + (d & 7) * 8 + (c & 7);
        WhHi[off] = __float2half(v);
    }
    if (tid < 24) {
        int u = tid / 3, gg = tid - u * 3;
        bhs[tid] = a.bh[gg * 512 + u0 + u];
    }
    // zero my slice of the parity-1 buffer (h_{-1} = 0)
    {
        int zn = 4096 / cpg;
        uint4 z; z.x = z.y = z.z = z.w = 0u;
        for (int i = tid; i < zn; i += 256) a.hb1[bl * zn + i] = z;
    }
    __syncthreads();
    if (tid == 0) st_rel(&a.flags[bl * FSTR], 1u);

    // per-thread constants
    const int kh = warp >> 2;      // K half (0/1)
    const int mt = warp & 3;       // mtile (rows mt*16..+15)
    const int g  = lane >> 3, r = lane & 7;
    const int g01 = g & 1;
    const int rowI = tid >> 3;     // gate item 0 row (0..31)
    const int uI   = tid & 7;
    const int cb   = uI * 3;
    const float bhr = bhs[cb], bhz = bhs[cb + 1], bhn = bhs[cb + 2];

    // poll addresses for warp 0 (2 slots per lane)
    const unsigned* fp0 = a.flags + (2 * lane) * FSTR;
    const unsigned* fp1 = a.flags + (2 * lane + 1) * FSTR;

    // producer scatter offsets (byte) for q=0,1
    int oQ[2];
    {
        int u = u0 + uI;
        int khp = u >> 8, ktp = (u >> 4) & 15, k_in = u & 15;
#pragma unroll
        for (int q = 0; q < 2; q++) {
            int row = rowI + q * 32;
            int mtp = row >> 4, m_in = row & 15;
            int lanep = (m_in & 7) * 4 + ((k_in & 7) >> 1);
            int regp = ((m_in >> 3) & 1) + (((k_in >> 3) & 1) << 1);
            oQ[q] = ((((khp * 16 + ktp) * 4 + mtp) * 32 + lanep) << 4)
                    + regp * 4 + (k_in & 1) * 2;
        }
    }
    float hp0 = 0.f, hp1 = 0.f;

    for (int s = 0; s < TT; s++) {
        float xw0r, xw0z, xw0n, xw1r, xw1z, xw1n;
        auto loadXW = [&]() {
            const float* p0 = a.XW + ((size_t)s * 64 + rowI) * G3 + u0 + uI;
            const float* p1 = p0 + (size_t)32 * G3;
            xw0r = p0[0]; xw0z = p0[512]; xw0n = p0[1024];
            xw1r = p1[0]; xw1z = p1[512]; xw1n = p1[1024];
        };
        // Prefetch XW before the poll whenever its readiness is already
        // known: always in static-XW mode; at odd steps in fused mode.
        const bool early = (!chunk) || (s & 1);
        if (early) loadXW();

        // wait: all h_{s-1} published (and XW chunk ready in fused mode)
        if (warp == 0) {
            const unsigned tgt = (unsigned)(s + 1);
            if (chunk && !(s & 1)) {
                const unsigned* cc = &chunk[s >> 1];
                for (;;) {
                    unsigned v0 = ld_acq(fp0);
                    unsigned v1 = ld_acq(fp1);
                    unsigned c0 = ld_acq(cc);
                    if (__all_sync(0xffffffffu,
                                   v0 >= tgt && v1 >= tgt && c0 >= 12u)) break;
                }
            } else {
                for (;;) {
                    unsigned v0 = ld_acq(fp0);
                    unsigned v1 = ld_acq(fp1);
                    if (__all_sync(0xffffffffu, v0 >= tgt && v1 >= tgt)) break;
                }
            }
        }
        __syncthreads();

        // prefetch ALL A-fragments (16 x LDG.128, MLP-batched)
        const uint4* rb = (s & 1) ? a.hb0 : a.hb1;
        uint4 AH[16];
        {
            const uint4* base = rb + (kh * 16 * 4 + mt) * 32 + lane;
#pragma unroll
            for (int kt = 0; kt < 16; kt++) AH[kt] = base[kt * 128];
        }
        if (!early) loadXW();   // fused even step: after chunk gate

        float acc[3][4];
#pragma unroll
        for (int nt = 0; nt < 3; nt++)
#pragma unroll
            for (int q = 0; q < 4; q++) acc[nt][q] = 0.f;

#pragma unroll
        for (int kt = 0; kt < 16; kt++) {
            const int k8a = kh * 32 + kt * 2;
            uint32_t bh6[6];
            {
                int k8 = k8a + (g & 1);
                int n8 = g >> 1;
                int elem = (k8 * 3 + n8) * 64 + r * 8;
                uint32_t bd = sptr(WhHi + elem);
                LDSM_X4T(bh6[0], bh6[1], bh6[2], bh6[3], bd);
                int k8c = k8a + g01;
                int elem2 = (k8c * 3 + 2) * 64 + r * 8;
                bd = sptr(WhHi + elem2);
                LDSM_X2T(bh6[4], bh6[5], bd);
            }
#pragma unroll
            for (int nt = 0; nt < 3; nt++) {
                float* c = acc[nt];
                MMAF16(c[0], c[1], c[2], c[3],
                       AH[kt].x, AH[kt].y, AH[kt].z, AH[kt].w,
                       bh6[nt * 2], bh6[nt * 2 + 1]);
            }
        }

        // write partials to smem
        {
            float* pb = part + kh * 1600;
            int prow = mt * 16 + (lane >> 2);
            int pc = (lane & 3) * 2;
#pragma unroll
            for (int nt = 0; nt < 3; nt++) {
                pb[prow * 25 + nt * 8 + pc]     = acc[nt][0];
                pb[prow * 25 + nt * 8 + pc + 1] = acc[nt][1];
                pb[(prow + 8) * 25 + nt * 8 + pc]     = acc[nt][2];
                pb[(prow + 8) * 25 + nt * 8 + pc + 1] = acc[nt][3];
            }
        }
        __syncthreads();

        // gates: 2 items per thread (rows rowI, rowI+32; unit uI)
        char* wb = (char*)((s & 1) ? a.hb1 : a.hb0);
        float hn0, hn1;
#pragma unroll
        for (int q = 0; q < 2; q++) {
            int row = rowI + q * 32;
            float gr = part[row * 25 + cb]     + part[1600 + row * 25 + cb];
            float gz = part[row * 25 + cb + 1] + part[1600 + row * 25 + cb + 1];
            float gn = part[row * 25 + cb + 2] + part[1600 + row * 25 + cb + 2];
            float xr = q ? xw1r : xw0r;
            float xz = q ? xw1z : xw0z;
            float xn = q ? xw1n : xw0n;
            float rr = __fdividef(1.f, 1.f + __expf(-(xr + gr + bhr)));
            float zz = __fdividef(1.f, 1.f + __expf(-(xz + gz + bhz)));
            float tt = xn + rr * (gn + bhn);
            float nn = __fdividef(2.f, 1.f + __expf(-2.f * tt)) - 1.f;
            float hp = q ? hp1 : hp0;
            float hn = (1.f - zz) * nn + zz * hp;
            if (q) { hp1 = hn; hn1 = hn; } else { hp0 = hn; hn0 = hn; }
            *(__half*)(wb + oQ[q]) = __float2half(hn);
        }
        __syncthreads();
        if (s < TT - 1 && tid == 0) st_rel(&a.flags[bl * FSTR], (unsigned)(s + 2));

        // OUT (f32) stores off the critical path
        const int oidx = a.rev ? (TT - 1 - s) : s;
        a.OUT[((size_t)oidx * NBATCH + rowI) * HID + u0 + uI] = hn0;
        a.OUT[((size_t)oidx * NBATCH + rowI + 32) * HID + u0 + uI] = hn1;
    }
}

__global__ __launch_bounds__(256, 1) void gru_tc(GruArgs a0, GruArgs a1, int cpg)
{
    extern __shared__ char smraw[];
    const bool second = (blockIdx.x / cpg) != 0;
    gru_scan(smraw, second ? a1 : a0, cpg, blockIdx.x % cpg, nullptr);
}

// Fused comm-layer kernel: CTAs 0..63 scan; CTAs 64..147 produce XW tiles in
// timestep order, publishing per-chunk (2 timesteps) ready counters.
__global__ __launch_bounds__(256, 1) void gru_fused(GruArgs a, ProdArgs pr)
{
    extern __shared__ char smraw[];
    if (blockIdx.x < 64) {
        gru_scan(smraw, a, 64, blockIdx.x, pr.chunk);
        return;
    }
    const int p = blockIdx.x - 64;
    for (int t = p; t < 3072; t += pr.nProd) {
        int c = t / 12, n = t - c * 12;
        tgemm_body<256>(smraw, pr.A, nullptr, pr.B, nullptr, pr.rowAdd, pr.C,
                        TT * NBATCH, HID, G3, 0, n, c);
        __syncthreads();
        if (threadIdx.x == 0) red_add_rel(&pr.chunk[c], 1u);
    }
}

// reset barrier flags + chunk counters for graph-replay determinism
__global__ void reset_flags_kernel()
{
    int i = blockIdx.x * blockDim.x + threadIdx.x;
    if (i < 4 * 64 * FSTR) ((unsigned*)g_flags)[i] = 0u;
    if (i < 4 * 256) ((unsigned*)g_chunk)[i] = 0u;
}

// ---------------------------------------------------------------------------
// msg / lasth
// ---------------------------------------------------------------------------
__global__ void msg_kernel(const float* __restrict__ h, float* __restrict__ msg)
{
    int idx = blockIdx.x * blockDim.x + threadIdx.x;
    if (idx >= NBATCH * HID) return;
    int n = idx >> 9, j = idx & 511;
    int b = n >> 3;
    float s = 0.f;
#pragma unroll
    for (int aa = 0; aa < AAGENT; aa++) s += h[((b << 3) + aa) * HID + j];
    msg[idx] = (s - h[n * HID + j]) * (1.f / (AAGENT - 1));
}

__global__ void lasth_kernel(const float* __restrict__ OUT, float* __restrict__ dst)
{
    int idx = blockIdx.x * blockDim.x + threadIdx.x;
    if (idx >= BBATCH * HID) return;
    int b = idx >> 9, j = idx & 511;
    dst[idx] = OUT[((size_t)(TT - 1) * NBATCH + b * AAGENT) * HID + j];
}

// ---------------------------------------------------------------------------
// launch
// ---------------------------------------------------------------------------
extern "C" void kernel_launch(void* const* d_in, const int* in_sizes, int n_in,
                              void* d_out, int out_size)
{
    const float* article = (const float*)d_in[0];
    const float* Wx_f = (const float*)d_in[2];
    const float* Wh_f = (const float*)d_in[3];
    const float* bx_f = (const float*)d_in[4];
    const float* bh_f = (const float*)d_in[5];
    const float* Wx_b = (const float*)d_in[6];
    const float* Wh_b = (const float*)d_in[7];
    const float* bx_b = (const float*)d_in[8];
    const float* bh_b = (const float*)d_in[9];
    const float* Wp   = (const float*)d_in[10];
    const float* bp   = (const float*)d_in[11];
    const float* Wm   = (const float*)d_in[12];
    const float* bm   = (const float*)d_in[13];
    const float* Wx_c = (const float*)d_in[14];
    const float* Wh_c = (const float*)d_in[15];
    const float* bx_c = (const float*)d_in[16];
    const float* bh_c = (const float*)d_in[17];

    float *XW1, *XW2, *ENCF, *ENCB, *ENC, *hsm, *msg, *msgrow;
    float *Wcomb, *Wm2f, *bfold;
    uint4* hfrag;
    unsigned *flags, *chunks;
    cudaGetSymbolAddress((void**)&XW1,  g_XW1);
    cudaGetSymbolAddress((void**)&XW2,  g_XW2);
    cudaGetSymbolAddress((void**)&ENCF, g_ENCF);
    cudaGetSymbolAddress((void**)&ENCB, g_ENCB);
    cudaGetSymbolAddress((void**)&ENC,  g_ENC);
    cudaGetSymbolAddress((void**)&hsm,  g_hsm);
    cudaGetSymbolAddress((void**)&msg,  g_msg);
    cudaGetSymbolAddress((void**)&msgrow, g_msgrow);
    cudaGetSymbolAddress((void**)&Wcomb, g_Wcomb);
    cudaGetSymbolAddress((void**)&Wm2f,  g_Wm2f);
    cudaGetSymbolAddress((void**)&bfold, g_bfold);
    cudaGetSymbolAddress((void**)&hfrag, g_hfrag);
    cudaGetSymbolAddress((void**)&flags, g_flags);
    cudaGetSymbolAddress((void**)&chunks, g_chunk);
    uint4* hA0 = hfrag;
    uint4* hA1 = hfrag + 4096;
    uint4* hB0 = hfrag + 8192;
    uint4* hB1 = hfrag + 12288;

    const int M = TT * NBATCH;
    const int SMG = 24576;
    cudaFuncSetAttribute((const void*)gru_tc,
                         cudaFuncAttributeMaxDynamicSharedMemorySize, S_TOTAL);
    cudaFuncSetAttribute((const void*)gru_fused,
                         cudaFuncAttributeMaxDynamicSharedMemorySize, S_TOTAL);

    // 0) weight folding (tiny):
    //    Wcomb[l] = Wm[:512] @ Wx_c[l]
    //    Wm2f[l]  = Wm[512:] @ Wx_c[l]
    //    bfold[l] = bm @ Wx_c[l] + bx_c[l]
    for (int l = 0; l < LLAYER; l++) {
        tgemm<<<dim3(12, 4), 256, SMG>>>(Wm, nullptr, Wx_c + (size_t)l * HID * G3,
                                         nullptr, nullptr,
                                         Wcomb + (size_t)l * HID * G3,
                                         HID, HID, G3, 0);
        tgemm<<<dim3(12, 4), 256, SMG>>>(Wm + (size_t)512 * HID, nullptr,
                                         Wx_c + (size_t)l * HID * G3,
                                         nullptr, nullptr,
                                         Wm2f + (size_t)l * HID * G3,
                                         HID, HID, G3, 0);
        tgemm<<<dim3(12, 1), 256, SMG>>>(bm, nullptr,
                                         Wx_c + (size_t)l * HID * G3,
                                         bx_c + (size_t)l * G3, nullptr,
                                         bfold + (size_t)l * G3,
                                         1, HID, G3, 0);
    }

    // 1) xW precompute for both directions (512-thread latency-optimized)
    tgemm512<<<dim3(G3 / 128, M / 128), 512, SMG>>>(article, nullptr, Wx_f, bx_f,
                                                    nullptr, XW1, M, DIN, G3, 0);
    tgemm512<<<dim3(G3 / 128, M / 128), 512, SMG>>>(article, nullptr, Wx_b, bx_b,
                                                    nullptr, XW2, M, DIN, G3, 1);

    // 2) bidirectional recurrence (two 64-CTA barrier groups, one launch)
    GruArgs af{XW1, Wh_f, bh_f, ENCF, hA0, hA1, flags + 0 * 64 * FSTR, 0};
    GruArgs ab{XW2, Wh_b, bh_b, ENCB, hB0, hB1, flags + 1 * 64 * FSTR, 1};
    gru_tc<<<128, 256, S_TOTAL>>>(af, ab, 64);

    // 3) projection of per-step encodings and of final hidden
    tgemm512<<<dim3(HID / 128, M / 128), 512, SMG>>>(ENCF, ENCB, Wp, bp, nullptr,
                                                     ENC, M, 2 * HID, HID, 0);
    tgemm<<<dim3(HID / 128, 1), 256, SMG>>>(ENCF + (size_t)(TT - 1) * NBATCH * HID,
                                            ENCB, Wp, bp, nullptr, hsm,
                                            NBATCH, 2 * HID, HID, 0);

    // 4) communication layers (fused producer/scanner); msgRow computed in a
    //    single folded GEMM: msgRow = msg @ Wm2f[l] + bfold[l]
    for (int l = 0; l < LLAYER; l++) {
        const float* hsrc = (l == 0) ? hsm : (ENC + (size_t)(TT - 1) * NBATCH * HID);
        msg_kernel<<<(NBATCH * HID) / 256, 256>>>(hsrc, msg);
        tgemm<<<dim3(G3 / 128, 1), 256, SMG>>>(msg, nullptr,
                                               Wm2f + (size_t)l * HID * G3,
                                               bfold + (size_t)l * G3, nullptr,
                                               msgrow, NBATCH, HID, G3, 0);
        float* outp = (l == LLAYER - 1) ? (float*)d_out : ENC;
        GruArgs ac{XW1, Wh_c + (size_t)l * HID * G3, bh_c + (size_t)l * G3,
                   outp, hA0, hA1, flags + (2 + l) * 64 * FSTR, 0};
        ProdArgs pc{ENC, Wcomb + (size_t)l * HID * G3, msgrow, XW1,
                    chunks + (2 + l) * 256, 84};
        gru_fused<<<148, 256, S_TOTAL>>>(ac, pc);
    }

    // 5) tail output + flag reset for graph replay
    lasth_kernel<<<(BBATCH * HID + 255) / 256, 256>>>(
        (const float*)d_out, (float*)d_out + (size_t)TT * NBATCH * HID);
    reset_flags_kernel<<<32, 256>>>();
}